// round 3
// baseline (speedup 1.0000x reference)
#include <cuda_runtime.h>
#include <cuda_bf16.h>

#define B_ROWS 16384
#define L_COLS 1024
#define ROWS_PER_BLK 8
#define NBLKS (B_ROWS / ROWS_PER_BLK)   // 2048

// Per-block partial sums of row losses + completion counter
// (no device allocation allowed; __device__ globals are the scratch).
__device__ float g_partials[NBLKS];
__device__ unsigned int g_count = 0;

// 2048 blocks x 256 threads. Warp w handles row blockIdx.x*8 + w.
// Each lane: 8 iterations of (float4 c, int4 y) -> 1024 elems/row.
// One __expf per element: e = exp(y ? -c : c).
// Last block to finish reduces all partials (fixed order -> deterministic),
// writes the mean, and resets the counter for graph replay.
__global__ void __launch_bounds__(256)
bpmll_fused_kernel(const float* __restrict__ c, const int* __restrict__ y,
                   float* __restrict__ out) {
    const int t = threadIdx.x;
    const int warp = t >> 5;
    const int lane = t & 31;
    const int row = blockIdx.x * ROWS_PER_BLK + warp;

    const float4* __restrict__ c4 =
        reinterpret_cast<const float4*>(c + (size_t)row * L_COLS);
    const int4* __restrict__ y4 =
        reinterpret_cast<const int4*>(y + (size_t)row * L_COLS);

    float pos = 0.0f, neg = 0.0f;
    int yc = 0;

    #pragma unroll
    for (int i = 0; i < 8; i++) {
        const float4 cv = c4[i * 32 + lane];
        const int4 yv = y4[i * 32 + lane];

        {
            const float e = __expf(yv.x ? -cv.x : cv.x);
            if (yv.x) { pos += e; yc++; } else { neg += e; }
        }
        {
            const float e = __expf(yv.y ? -cv.y : cv.y);
            if (yv.y) { pos += e; yc++; } else { neg += e; }
        }
        {
            const float e = __expf(yv.z ? -cv.z : cv.z);
            if (yv.z) { pos += e; yc++; } else { neg += e; }
        }
        {
            const float e = __expf(yv.w ? -cv.w : cv.w);
            if (yv.w) { pos += e; yc++; } else { neg += e; }
        }
    }

    // Warp tree reduction (deterministic).
    #pragma unroll
    for (int off = 16; off > 0; off >>= 1) {
        pos += __shfl_down_sync(0xFFFFFFFFu, pos, off);
        neg += __shfl_down_sync(0xFFFFFFFFu, neg, off);
        yc  += __shfl_down_sync(0xFFFFFFFFu, yc, off);
    }

    __shared__ float s_loss[ROWS_PER_BLK];
    __shared__ bool s_is_last;
    if (lane == 0) {
        const float yn = (float)yc;
        const float ybn = (float)(L_COLS - yc);
        s_loss[warp] = (pos * neg) / (yn * ybn);
    }
    __syncthreads();

    if (t == 0) {
        float sum = 0.0f;
        #pragma unroll
        for (int w = 0; w < ROWS_PER_BLK; w++) sum += s_loss[w];
        g_partials[blockIdx.x] = sum;
        __threadfence();  // make partial visible before signaling
        const unsigned int prev = atomicAdd(&g_count, 1u);
        s_is_last = (prev == (unsigned int)(NBLKS - 1));
    }
    __syncthreads();

    if (s_is_last) {
        // Final reduction over 2048 partials (L2-hot). 256 threads x 8 each,
        // fixed order -> bitwise deterministic.
        float s = 0.0f;
        const float4* p4 = reinterpret_cast<const float4*>(g_partials);
        #pragma unroll
        for (int i = 0; i < 2; i++) {
            const float4 v = p4[i * 256 + t];   // 512 float4 = 2048 floats
            s += (v.x + v.y) + (v.z + v.w);
        }

        #pragma unroll
        for (int off = 16; off > 0; off >>= 1)
            s += __shfl_down_sync(0xFFFFFFFFu, s, off);

        __shared__ float s_w[8];
        if (lane == 0) s_w[warp] = s;
        __syncthreads();

        if (t == 0) {
            float tot = 0.0f;
            #pragma unroll
            for (int w = 0; w < 8; w++) tot += s_w[w];
            out[0] = tot * (1.0f / (float)B_ROWS);
            g_count = 0;  // reset for next graph replay
        }
    }
}

extern "C" void kernel_launch(void* const* d_in, const int* in_sizes, int n_in,
                              void* d_out, int out_size) {
    const float* c = (const float*)d_in[0];
    const int* y = (const int*)d_in[1];
    float* out = (float*)d_out;

    bpmll_fused_kernel<<<NBLKS, 256>>>(c, y, out);
}

// round 7
// speedup vs baseline: 1.0515x; 1.0515x over previous
#include <cuda_runtime.h>
#include <cuda_bf16.h>

#define B_ROWS 16384
#define L_COLS 1024
#define ROWS_PER_BLK 8
#define NBLKS (B_ROWS / ROWS_PER_BLK)   // 2048

// Per-block partial sums of row losses (no device allocation allowed).
__device__ float g_partials[NBLKS];

// 2048 blocks x 256 threads. Warp w handles row blockIdx.x*8 + w.
// Each lane: 8 iterations of (float4 c, int4 y) -> 1024 elems/row.
// One __expf per element: e = exp(y ? -c : c).
__global__ void __launch_bounds__(256)
bpmll_row_kernel(const float* __restrict__ c, const int* __restrict__ y,
                 float* __restrict__ partials) {
    const int t = threadIdx.x;
    const int warp = t >> 5;
    const int lane = t & 31;
    const int row = blockIdx.x * ROWS_PER_BLK + warp;

    const float4* __restrict__ c4 =
        reinterpret_cast<const float4*>(c + (size_t)row * L_COLS);
    const int4* __restrict__ y4 =
        reinterpret_cast<const int4*>(y + (size_t)row * L_COLS);

    float pos = 0.0f, neg = 0.0f;
    int yc = 0;

    #pragma unroll
    for (int i = 0; i < 8; i++) {
        const float4 cv = c4[i * 32 + lane];
        const int4 yv = y4[i * 32 + lane];

        {
            const float e = __expf(yv.x ? -cv.x : cv.x);
            if (yv.x) { pos += e; yc++; } else { neg += e; }
        }
        {
            const float e = __expf(yv.y ? -cv.y : cv.y);
            if (yv.y) { pos += e; yc++; } else { neg += e; }
        }
        {
            const float e = __expf(yv.z ? -cv.z : cv.z);
            if (yv.z) { pos += e; yc++; } else { neg += e; }
        }
        {
            const float e = __expf(yv.w ? -cv.w : cv.w);
            if (yv.w) { pos += e; yc++; } else { neg += e; }
        }
    }

    // Warp tree reduction (deterministic).
    #pragma unroll
    for (int off = 16; off > 0; off >>= 1) {
        pos += __shfl_down_sync(0xFFFFFFFFu, pos, off);
        neg += __shfl_down_sync(0xFFFFFFFFu, neg, off);
        yc  += __shfl_down_sync(0xFFFFFFFFu, yc, off);
    }

    __shared__ float s_loss[ROWS_PER_BLK];
    const int lwarp = warp;
    if (lane == 0) {
        const float yn = (float)yc;
        const float ybn = (float)(L_COLS - yc);
        s_loss[lwarp] = (pos * neg) / (yn * ybn);
    }
    __syncthreads();

    if (t == 0) {
        float sum = 0.0f;
        #pragma unroll
        for (int w = 0; w < ROWS_PER_BLK; w++) sum += s_loss[w];
        partials[blockIdx.x] = sum;
    }
    // Let the dependent reduce kernel begin launching as early as possible.
    cudaTriggerProgrammaticLaunchCompletion();
}

// Single-block reduction of 2048 partials -> mean over 16384 rows.
// Launched with PDL; waits on the primary grid before reading partials.
__global__ void __launch_bounds__(512)
bpmll_reduce_kernel(const float* __restrict__ partials, float* __restrict__ out) {
    cudaGridDependencySynchronize();

    const int t = threadIdx.x;
    const float4 v = reinterpret_cast<const float4*>(partials)[t];  // 512*4 = 2048
    float s = (v.x + v.y) + (v.z + v.w);

    #pragma unroll
    for (int off = 16; off > 0; off >>= 1)
        s += __shfl_down_sync(0xFFFFFFFFu, s, off);

    __shared__ float s_w[16];
    const int warp = t >> 5;
    const int lane = t & 31;
    if (lane == 0) s_w[warp] = s;
    __syncthreads();

    if (t == 0) {
        float tot = 0.0f;
        #pragma unroll
        for (int w = 0; w < 16; w++) tot += s_w[w];
        out[0] = tot * (1.0f / (float)B_ROWS);
    }
}

extern "C" void kernel_launch(void* const* d_in, const int* in_sizes, int n_in,
                              void* d_out, int out_size) {
    const float* c = (const float*)d_in[0];
    const int* y = (const int*)d_in[1];
    float* out = (float*)d_out;

    float* partials = nullptr;
    cudaGetSymbolAddress((void**)&partials, g_partials);

    bpmll_row_kernel<<<NBLKS, 256>>>(c, y, partials);

    // Secondary launch with programmatic dependent launch (overlaps launch
    // setup with the primary kernel's drain).
    cudaLaunchConfig_t cfg = {};
    cfg.gridDim = dim3(1, 1, 1);
    cfg.blockDim = dim3(512, 1, 1);
    cfg.dynamicSmemBytes = 0;
    cfg.stream = 0;
    cudaLaunchAttribute attrs[1];
    attrs[0].id = cudaLaunchAttributeProgrammaticStreamSerialization;
    attrs[0].val.programmaticStreamSerializationAllowed = 1;
    cfg.attrs = attrs;
    cfg.numAttrs = 1;
    cudaLaunchKernelEx(&cfg, bpmll_reduce_kernel,
                       (const float*)partials, out);
}

// round 9
// speedup vs baseline: 1.0767x; 1.0240x over previous
#include <cuda_runtime.h>
#include <cuda_bf16.h>

#define B_ROWS 16384
#define L_COLS 1024
#define ROWS_PER_BLK 16
#define NBLKS (B_ROWS / ROWS_PER_BLK)   // 1024

// Per-block partial sums of row losses (no device allocation allowed).
__device__ float g_partials[NBLKS];

// 1024 blocks x 512 threads (16 warps). Warp w handles row blockIdx.x*16 + w.
// Each lane: 8 iterations of (float4 c, int4 y) -> 1024 elems/row.
// launch_bounds(512, 4) caps regs at 32 -> 4 blocks/SM -> 100% occupancy.
__global__ void __launch_bounds__(512, 4)
bpmll_row_kernel(const float* __restrict__ c, const int* __restrict__ y,
                 float* __restrict__ partials) {
    const int t = threadIdx.x;
    const int warp = t >> 5;
    const int lane = t & 31;
    const int row = blockIdx.x * ROWS_PER_BLK + warp;

    const float4* __restrict__ c4 =
        reinterpret_cast<const float4*>(c + (size_t)row * L_COLS);
    const int4* __restrict__ y4 =
        reinterpret_cast<const int4*>(y + (size_t)row * L_COLS);

    float pos = 0.0f, neg = 0.0f;
    int yc = 0;

    #pragma unroll
    for (int i = 0; i < 8; i++) {
        const float4 cv = c4[i * 32 + lane];
        const int4 yv = y4[i * 32 + lane];

        {
            const float e = __expf(yv.x ? -cv.x : cv.x);
            if (yv.x) { pos += e; yc++; } else { neg += e; }
        }
        {
            const float e = __expf(yv.y ? -cv.y : cv.y);
            if (yv.y) { pos += e; yc++; } else { neg += e; }
        }
        {
            const float e = __expf(yv.z ? -cv.z : cv.z);
            if (yv.z) { pos += e; yc++; } else { neg += e; }
        }
        {
            const float e = __expf(yv.w ? -cv.w : cv.w);
            if (yv.w) { pos += e; yc++; } else { neg += e; }
        }
    }

    // Warp tree reduction (deterministic).
    #pragma unroll
    for (int off = 16; off > 0; off >>= 1) {
        pos += __shfl_down_sync(0xFFFFFFFFu, pos, off);
        neg += __shfl_down_sync(0xFFFFFFFFu, neg, off);
        yc  += __shfl_down_sync(0xFFFFFFFFu, yc, off);
    }

    __shared__ float s_loss[ROWS_PER_BLK];
    if (lane == 0) {
        const float yn = (float)yc;
        const float ybn = (float)(L_COLS - yc);
        s_loss[warp] = (pos * neg) / (yn * ybn);
    }
    __syncthreads();

    if (t == 0) {
        float sum = 0.0f;
        #pragma unroll
        for (int w = 0; w < ROWS_PER_BLK; w++) sum += s_loss[w];
        partials[blockIdx.x] = sum;
    }
    cudaTriggerProgrammaticLaunchCompletion();
}

// Single-block reduction of 1024 partials -> mean over 16384 rows.
// Launched with PDL; waits on the primary grid before reading partials.
__global__ void __launch_bounds__(256)
bpmll_reduce_kernel(const float* __restrict__ partials, float* __restrict__ out) {
    cudaGridDependencySynchronize();

    const int t = threadIdx.x;
    const float4 v = reinterpret_cast<const float4*>(partials)[t];  // 256*4 = 1024
    float s = (v.x + v.y) + (v.z + v.w);

    #pragma unroll
    for (int off = 16; off > 0; off >>= 1)
        s += __shfl_down_sync(0xFFFFFFFFu, s, off);

    __shared__ float s_w[8];
    const int warp = t >> 5;
    const int lane = t & 31;
    if (lane == 0) s_w[warp] = s;
    __syncthreads();

    if (t == 0) {
        float tot = 0.0f;
        #pragma unroll
        for (int w = 0; w < 8; w++) tot += s_w[w];
        out[0] = tot * (1.0f / (float)B_ROWS);
    }
}

extern "C" void kernel_launch(void* const* d_in, const int* in_sizes, int n_in,
                              void* d_out, int out_size) {
    const float* c = (const float*)d_in[0];
    const int* y = (const int*)d_in[1];
    float* out = (float*)d_out;

    float* partials = nullptr;
    cudaGetSymbolAddress((void**)&partials, g_partials);

    bpmll_row_kernel<<<NBLKS, 512>>>(c, y, partials);

    cudaLaunchConfig_t cfg = {};
    cfg.gridDim = dim3(1, 1, 1);
    cfg.blockDim = dim3(256, 1, 1);
    cfg.dynamicSmemBytes = 0;
    cfg.stream = 0;
    cudaLaunchAttribute attrs[1];
    attrs[0].id = cudaLaunchAttributeProgrammaticStreamSerialization;
    attrs[0].val.programmaticStreamSerializationAllowed = 1;
    cfg.attrs = attrs;
    cfg.numAttrs = 1;
    cudaLaunchKernelEx(&cfg, bpmll_reduce_kernel,
                       (const float*)partials, out);
}